// round 8
// baseline (speedup 1.0000x reference)
#include <cuda_runtime.h>
#include <cuda_bf16.h>
#include <stdint.h>

// Problem constants (fixed by reference: B=16, NT=4096, D=512, V=2545)
#define B_  16
#define NT_ 4096
#define D_  512
#define V_  2545
#define D_VEC (D_ / 4)               // 128 float4 per embedding row
#define NROWS (B_ * NT_)             // 65536 output rows
#define CHUNKS_PER_B 8               // prep chunks per batch row
#define NPREP (B_ * CHUNKS_PER_B)    // 128 prep blocks
#define CHUNK (NT_ / CHUNKS_PER_B)   // 512 positions per prep chunk

// Scratch (device allocations forbidden -> __device__ globals)
__device__ int g_tok[NROWS];   // source token per output row (+1 applied), or -1 => zeros
__device__ unsigned g_done;    // monotonic prep-completion counter (zero-init at load)

// ---------------------------------------------------------------------------
// Single fused kernel. grid = NROWS/8 = 8192 blocks x 256 threads.
//
// Blocks 0..127 first run the PREP phase (dtype probe, valid-token count for
// their batch, stretch mapping for their 512-position chunk -> g_tok), then
// fence + atomicAdd(g_done). ALL blocks gate the copy phase on
// g_done >= 128.
//
// Safety: prep bids 0..127 are always within scheduling wave 1 (~1180 blocks
// resident), so pollers never starve the producers -> no deadlock.
// Replays: g_done stays >= 128 so the gate is free, and g_tok is recomputed
// to identical values (same inputs), so any interleaving reads correct data.
// L1 is flushed at launch boundaries, so no stale-L1 hazard on the gate.
//
// Copy phase (proven R3 config): 2 groups of 128 lanes per block, group
// copies rows rowBase + {0,2,4,6} — 4 independent float4 loads (MLP=4),
// then 4 streaming stores.
// ---------------------------------------------------------------------------
__global__ void __launch_bounds__(256)
fused_embed_kernel(const int* __restrict__ t32,
                   const float4* __restrict__ emb,
                   float4* __restrict__ out) {
    const int bid = blockIdx.x;
    const int tid = threadIdx.x;

    if (bid < NPREP) {
        // ---------------- PREP PHASE ----------------
        const int b     = bid >> 3;
        const int chunk = bid & 7;

        // dtype probe: first 256 int32-word pairs as little-endian int64?
        int bad = 0;
        {
            const int lo = t32[2 * tid];
            const int hi = t32[2 * tid + 1];
            const int want_hi = (lo < 0) ? -1 : 0;
            if (hi != want_hi || lo < -1 || lo >= V_) bad = 1;
        }
        const int is64 = __syncthreads_or(bad) ? 0 : 1;
        const int stride = is64 ? 2 : 1;
        const int* row = t32 + (size_t)b * NT_ * stride;

        // count valid tokens (valid = token >= 0)
        int cnt = 0;
        #pragma unroll
        for (int i = tid; i < NT_; i += 256)
            cnt += (row[(size_t)i * stride] >= 0);
        #pragma unroll
        for (int off = 16; off > 0; off >>= 1)
            cnt += __shfl_down_sync(0xFFFFFFFFu, cnt, off);

        __shared__ int s_part[8];
        if ((tid & 31) == 0) s_part[tid >> 5] = cnt;
        __syncthreads();
        __shared__ int s_L;
        if (tid == 0) {
            int total = 0;
            for (int w = 0; w < 8; ++w) total += s_part[w];
            s_L = total;
        }
        __syncthreads();
        const int L = s_L;

        // stretch mapping for this chunk's 512 positions (2 per thread)
        int* tok_row = g_tok + b * NT_;
        const int p0 = chunk * CHUNK;
        if (L <= 0) {
            tok_row[p0 + tid]       = -1;
            tok_row[p0 + tid + 256] = -1;
        } else {
            const unsigned base = (unsigned)NT_ / (unsigned)L;
            const unsigned rem  = (unsigned)NT_ % (unsigned)L;
            const unsigned boundary = ((unsigned)L - rem) * base;
            #pragma unroll
            for (int q = 0; q < 2; ++q) {
                const unsigned p = (unsigned)(p0 + tid + q * 256);
                unsigned j;
                if (p < boundary) j = p / base;
                else              j = ((unsigned)L - rem) + (p - boundary) / (base + 1);
                int t = row[(size_t)j * stride] + 1;   // [1, V] for valid prefix
                tok_row[p] = min(max(t, 0), V_);       // hard safety clamp
            }
        }

        __threadfence();           // publish g_tok before signaling
        __syncthreads();
        if (tid == 0) atomicAdd(&g_done, 1u);
    }

    // ---------------- GATE ----------------
    if (tid == 0) {
        while (*(volatile unsigned*)&g_done < (unsigned)NPREP)
            __nanosleep(128);
    }
    __syncthreads();               // block-wide: copy phase ordered after gate
    __threadfence();               // acquire side of the flag handshake

    // ---------------- COPY PHASE ----------------
    const int lane = tid & 127;
    const int sub  = tid >> 7;     // 0 or 1
    const int rowBase = bid * 8 + sub;

    int tok[4];
    #pragma unroll
    for (int k = 0; k < 4; ++k)
        tok[k] = __ldg(&g_tok[rowBase + 2 * k]);

    float4 v[4];
    #pragma unroll
    for (int k = 0; k < 4; ++k) {
        if (tok[k] >= 0)
            v[k] = __ldg(emb + (size_t)tok[k] * D_VEC + lane);
        else
            v[k] = make_float4(0.f, 0.f, 0.f, 0.f);
    }

    #pragma unroll
    for (int k = 0; k < 4; ++k)
        __stcs(out + (size_t)(rowBase + 2 * k) * D_VEC + lane, v[k]);
}

// ---------------------------------------------------------------------------
// Launch. Identify inputs by element count:
//   text: 65536 elements (int32 or int64) or 131072 int32-words; the
//         device-side probe resolves the layout.
//   emb : (2545+1)*512 = 1303552 fp32.
// ---------------------------------------------------------------------------
extern "C" void kernel_launch(void* const* d_in, const int* in_sizes, int n_in,
                              void* d_out, int out_size) {
    const int*   text = nullptr;
    const float* emb  = nullptr;
    for (int i = 0; i < n_in; ++i) {
        if (in_sizes[i] == NROWS || in_sizes[i] == 2 * NROWS)
            text = (const int*)d_in[i];
        else if (in_sizes[i] == (V_ + 1) * D_)
            emb = (const float*)d_in[i];
    }

    fused_embed_kernel<<<NROWS / 8, 256>>>(text, (const float4*)emb, (float4*)d_out);
    (void)out_size;
}

// round 9
// speedup vs baseline: 1.1517x; 1.1517x over previous
#include <cuda_runtime.h>
#include <cuda_bf16.h>
#include <stdint.h>

// Problem constants (fixed by reference: B=16, NT=4096, D=512, V=2545)
#define B_  16
#define NT_ 4096
#define D_  512
#define V_  2545
#define D_VEC (D_ / 4)               // 128 float4 per embedding row
#define NROWS (B_ * NT_)             // 65536 output rows
#define CHUNKS_PER_B 8               // prep blocks per batch row
#define NPREP (B_ * CHUNKS_PER_B)    // 128 prep blocks
#define CHUNK (NT_ / CHUNKS_PER_B)   // 512 positions per prep chunk

// Scratch (device allocations forbidden -> __device__ global)
__device__ int g_tok[NROWS];   // source token per output row (+1 applied), or -1 => zeros

// ---------------------------------------------------------------------------
// Prep kernel: 128 blocks (8 chunks x 16 batches), 512 threads.
//  (a) dtype probe (int64 little-endian word-pairs vs int32);
//  (b) valid-token count L_b (redundant per chunk-block — cheap, L2-resident);
//  (c) stretch mapping for this block's 512 positions -> g_tok.
// Ends with cudaTriggerProgrammaticLaunchCompletion() so the dependent embed
// kernel's launch overlaps our tail.
// ---------------------------------------------------------------------------
__global__ void __launch_bounds__(512)
prep_kernel(const int* __restrict__ t32) {
    const int b     = blockIdx.x >> 3;
    const int chunk = blockIdx.x & 7;
    const int tid   = threadIdx.x;

    // --- dtype probe ---
    int bad = 0;
    if (tid < 256) {
        const int lo = t32[2 * tid];
        const int hi = t32[2 * tid + 1];
        const int want_hi = (lo < 0) ? -1 : 0;
        if (hi != want_hi || lo < -1 || lo >= V_) bad = 1;
    }
    const int is64 = __syncthreads_or(bad) ? 0 : 1;
    const int stride = is64 ? 2 : 1;
    const int* row = t32 + (size_t)b * NT_ * stride;

    // --- count valid tokens (valid = token >= 0) ---
    int cnt = 0;
    #pragma unroll
    for (int i = tid; i < NT_; i += 512)
        cnt += (row[(size_t)i * stride] >= 0);
    #pragma unroll
    for (int off = 16; off > 0; off >>= 1)
        cnt += __shfl_down_sync(0xFFFFFFFFu, cnt, off);

    __shared__ int s_part[16];
    if ((tid & 31) == 0) s_part[tid >> 5] = cnt;
    __syncthreads();
    __shared__ int s_L;
    if (tid == 0) {
        int total = 0;
        for (int w = 0; w < 16; ++w) total += s_part[w];
        s_L = total;
    }
    __syncthreads();
    const int L = s_L;

    // --- stretch mapping for this chunk's 512 positions (1 per thread) ---
    const int p = chunk * CHUNK + tid;
    int* tok_row = g_tok + b * NT_;
    if (L <= 0) {
        tok_row[p] = -1;
    } else {
        const unsigned base = (unsigned)NT_ / (unsigned)L;
        const unsigned rem  = (unsigned)NT_ % (unsigned)L;
        const unsigned boundary = ((unsigned)L - rem) * base;
        unsigned j;
        if ((unsigned)p < boundary) j = (unsigned)p / base;
        else                        j = ((unsigned)L - rem) + ((unsigned)p - boundary) / (base + 1);
        int t = row[(size_t)j * stride] + 1;    // [1, V] for valid prefix
        tok_row[p] = min(max(t, 0), V_);        // hard safety clamp
    }

#if defined(__CUDA_ARCH__) && (__CUDA_ARCH__ >= 900)
    // Let the dependent embed kernel begin launching now; its
    // cudaGridDependencySynchronize() still waits for our full completion
    // (memory visibility included).
    cudaTriggerProgrammaticLaunchCompletion();
#endif
}

// ---------------------------------------------------------------------------
// Embed kernel: pure gather-copy, proven R3/R7 configuration, with a
// hardware PDL dependency wait at entry (not a software poll).
// 256 threads/block handle 8 rows: thread t owns lane = t & 127 of rows
// rowBase + (t>>7) + {0,2,4,6}. MLP=4 loads, then 4 streaming stores.
// grid = NROWS / 8 = 8192 blocks.
// ---------------------------------------------------------------------------
__global__ void __launch_bounds__(256)
embed_copy_kernel(const float4* __restrict__ emb,
                  float4* __restrict__ out) {
#if defined(__CUDA_ARCH__) && (__CUDA_ARCH__ >= 900)
    cudaGridDependencySynchronize();   // wait for prep completion (HW, cheap)
#endif

    const int lane = threadIdx.x & 127;
    const int sub  = threadIdx.x >> 7;          // 0 or 1
    const int rowBase = blockIdx.x * 8 + sub;

    int tok[4];
    #pragma unroll
    for (int k = 0; k < 4; ++k)
        tok[k] = __ldg(&g_tok[rowBase + 2 * k]);

    float4 v[4];
    #pragma unroll
    for (int k = 0; k < 4; ++k) {
        if (tok[k] >= 0)
            v[k] = __ldg(emb + (size_t)tok[k] * D_VEC + lane);
        else
            v[k] = make_float4(0.f, 0.f, 0.f, 0.f);
    }

    #pragma unroll
    for (int k = 0; k < 4; ++k)
        __stcs(out + (size_t)(rowBase + 2 * k) * D_VEC + lane, v[k]);
}

// ---------------------------------------------------------------------------
// Launch: prep normally, embed via cudaLaunchKernelEx with
// programmatic-stream-serialization so its launch overlaps prep's execution.
// Both are plain kernel launches — graph-capturable, no allocations.
// ---------------------------------------------------------------------------
extern "C" void kernel_launch(void* const* d_in, const int* in_sizes, int n_in,
                              void* d_out, int out_size) {
    const int*   text = nullptr;
    const float* emb  = nullptr;
    for (int i = 0; i < n_in; ++i) {
        if (in_sizes[i] == NROWS || in_sizes[i] == 2 * NROWS)
            text = (const int*)d_in[i];
        else if (in_sizes[i] == (V_ + 1) * D_)
            emb = (const float*)d_in[i];
    }

    prep_kernel<<<NPREP, 512>>>(text);

    cudaLaunchConfig_t cfg = {};
    cfg.gridDim  = dim3(NROWS / 8, 1, 1);
    cfg.blockDim = dim3(256, 1, 1);
    cfg.dynamicSmemBytes = 0;
    cfg.stream = 0;
    cudaLaunchAttribute attr[1];
    attr[0].id = cudaLaunchAttributeProgrammaticStreamSerialization;
    attr[0].val.programmaticStreamSerializationAllowed = 1;
    cfg.attrs = attr;
    cfg.numAttrs = 1;

    const float4* emb4 = (const float4*)emb;
    float4* out4 = (float4*)d_out;
    cudaError_t e = cudaLaunchKernelEx(&cfg, embed_copy_kernel, emb4, out4);
    if (e != cudaSuccess) {
        // Fallback: plain dependent launch (still correct, just no overlap).
        embed_copy_kernel<<<NROWS / 8, 256>>>(emb4, out4);
    }
    (void)out_size;
}